// round 1
// baseline (speedup 1.0000x reference)
#include <cuda_runtime.h>
#include <cuda_bf16.h>
#include <cstdint>

// Problem constants (fixed by the reference)
#define N_COLS  22
#define N_PAIRS 231
#define EMB     12
#define DVEC    64
#define N_PRIM  5
#define COMBO2  (EMB * EMB * 2)   // 288 floats per pair in the LUT

// Scratch: precomputed per-pair lookup table T[p][fi][fj][o]  (266 KB)
__device__ __align__(16) float g_T[N_PAIRS * COMBO2];

// ---------------------------------------------------------------------------
// Kernel 1: build T[p, fi, fj, o] = sum_d w_sel[p,o,d] * op_sel(ti[fi,d], tj[fj,d])
// One block per pair; 288 threads, one per (fi, fj, o) task.
// ---------------------------------------------------------------------------
__global__ __launch_bounds__(COMBO2)
void build_lut_kernel(const float* __restrict__ tables,
                      const float* __restrict__ Wsmall,
                      const float* __restrict__ Wconcat,
                      const float* __restrict__ aw)
{
    const int p = blockIdx.x;

    // pair p -> (i, j) of triu(N_COLS, k=1), row-major order
    int i = 0, r = p, c = N_COLS - 1;
    while (r >= c) { r -= c; ++i; --c; }
    const int j = i + 1 + r;

    // selected primitive (arch_weights is exact one-hot of 0.0 / 1.0)
    int k = 0;
#pragma unroll
    for (int t = 0; t < N_PRIM; ++t)
        if (aw[p * N_PRIM + t] > 0.5f) k = t;

    // stage the 12 candidate embedding vectors for columns i and j
    __shared__ float shi[EMB][DVEC + 1];   // +1 pad: kill 64-float-stride bank conflicts
    __shared__ float shj[EMB][DVEC + 1];
    for (int e = threadIdx.x; e < EMB * DVEC; e += blockDim.x) {
        const int row = e >> 6, d = e & 63;
        shi[row][d] = tables[(i * EMB + row) * DVEC + d];
        shj[row][d] = tables[(j * EMB + row) * DVEC + d];
    }
    __syncthreads();

    const int task  = threadIdx.x;          // 0..287
    const int o     = task & 1;
    const int combo = task >> 1;            // fi*12 + fj
    const int fi    = combo / EMB;
    const int fj    = combo - fi * EMB;

    float acc = 0.0f;
    if (k == 4) {
        const float* w = Wconcat + (p * 2 + o) * (2 * DVEC);
#pragma unroll
        for (int d = 0; d < DVEC; ++d)
            acc += __ldg(&w[d]) * shi[fi][d] + __ldg(&w[DVEC + d]) * shj[fj][d];
    } else {
        const float* w = Wsmall + ((p * 4 + k) * 2 + o) * DVEC;
        if (k == 0) {
#pragma unroll
            for (int d = 0; d < DVEC; ++d)
                acc += __ldg(&w[d]) * (shi[fi][d] + shj[fj][d]);
        } else if (k == 1) {
#pragma unroll
            for (int d = 0; d < DVEC; ++d)
                acc += __ldg(&w[d]) * (shi[fi][d] * shj[fj][d]);
        } else if (k == 2) {
#pragma unroll
            for (int d = 0; d < DVEC; ++d)
                acc += __ldg(&w[d]) * fmaxf(shi[fi][d], shj[fj][d]);
        } else {
#pragma unroll
            for (int d = 0; d < DVEC; ++d)
                acc += __ldg(&w[d]) * fminf(shi[fi][d], shj[fj][d]);
        }
    }
    g_T[p * COMBO2 + task] = acc;
}

// ---------------------------------------------------------------------------
// Kernel 2: out[b, :] = sum_p T[p, f[i_p], f[j_p], :]
// Block = 128 threads: lane (0..31) = batch element within block,
//                      chunk (0..3) = pair range (58/58/58/57).
// Each thread gathers float2 from g_T; warp lanes hit the same pair's 1.15 KB
// region (high L1 sector overlap). Cross-chunk reduce through SMEM.
// ---------------------------------------------------------------------------
__global__ __launch_bounds__(128)
void accumulate_kernel(const int* __restrict__ feats,
                       float* __restrict__ out,
                       int B)
{
    __shared__ int    shf[32][N_COLS + 1];   // +1 pad -> stride 23 (coprime w/ 32 banks)
    __shared__ uchar2 shp[N_PAIRS + 1];
    __shared__ float2 shred[4][32];

    const int tid   = threadIdx.x;
    const int lane  = tid & 31;
    const int chunk = tid >> 5;
    const int bbase = blockIdx.x * 32;

    // cooperative, coalesced load of 32 feats rows
    for (int e = tid; e < 32 * N_COLS; e += 128) {
        const int row = e / N_COLS, col = e - row * N_COLS;
        const int b   = bbase + row;
        shf[row][col] = (b < B) ? feats[b * N_COLS + col] : 0;
    }
    // build (i, j) pair byte table
    for (int p = tid; p < N_PAIRS; p += 128) {
        int i = 0, r = p, c = N_COLS - 1;
        while (r >= c) { r -= c; ++i; --c; }
        shp[p] = make_uchar2((unsigned char)i, (unsigned char)(i + 1 + r));
    }
    __syncthreads();

    // this thread's pair range
    const int p0 = chunk * 58;
    const int p1 = (chunk == 3) ? N_PAIRS : p0 + 58;

    const float2* __restrict__ T2 = (const float2*)g_T;
    float2 a0 = make_float2(0.f, 0.f);
    float2 a1 = make_float2(0.f, 0.f);

#pragma unroll 2
    for (int p = p0; p < p1; ++p) {
        const uchar2 ij  = shp[p];
        const int    idx = shf[lane][ij.x] * EMB + shf[lane][ij.y];
        const float2 v   = __ldg(&T2[p * (EMB * EMB) + idx]);
        if (p & 1) { a1.x += v.x; a1.y += v.y; }
        else       { a0.x += v.x; a0.y += v.y; }
    }
    a0.x += a1.x; a0.y += a1.y;

    shred[chunk][lane] = a0;
    __syncthreads();

    if (chunk == 0) {
        float2 s = shred[0][lane];
        const float2 s1 = shred[1][lane];
        const float2 s2 = shred[2][lane];
        const float2 s3 = shred[3][lane];
        s.x += s1.x + s2.x + s3.x;
        s.y += s1.y + s2.y + s3.y;
        const int b = bbase + lane;
        if (b < B) ((float2*)out)[b] = s;
    }
}

// ---------------------------------------------------------------------------
// Launch: two kernels on the default stream (implicit ordering), graph-safe.
// Inputs (metadata order): feats(i32), tables(f32), W_small(f32),
//                          W_concat(f32), arch_weights(f32)
// ---------------------------------------------------------------------------
extern "C" void kernel_launch(void* const* d_in, const int* in_sizes, int n_in,
                              void* d_out, int out_size)
{
    const int*   feats   = (const int*)  d_in[0];
    const float* tables  = (const float*)d_in[1];
    const float* Wsmall  = (const float*)d_in[2];
    const float* Wconcat = (const float*)d_in[3];
    const float* aw      = (const float*)d_in[4];
    float*       out     = (float*)d_out;

    const int B = in_sizes[0] / N_COLS;   // 4096

    build_lut_kernel<<<N_PAIRS, COMBO2>>>(tables, Wsmall, Wconcat, aw);

    const int nblocks = (B + 31) / 32;
    accumulate_kernel<<<nblocks, 128>>>(feats, out, B);
}

// round 2
// speedup vs baseline: 1.3848x; 1.3848x over previous
#include <cuda_runtime.h>
#include <cuda_bf16.h>
#include <cstdint>

// Problem constants (fixed by the reference)
#define N_COLS  22
#define N_PAIRS 231
#define EMB     12
#define DVEC    64
#define N_PRIM  5
#define COMBO2  (EMB * EMB * 2)   // 288 floats per pair in the LUT

// Scratch: precomputed per-pair lookup table T[p][fi][fj][o]  (266 KB)
__device__ __align__(16) float g_T[N_PAIRS * COMBO2];

// ---------------------------------------------------------------------------
// Kernel 1: build T[p, fi, fj, o] = sum_d w_sel[p,o,d] * op_sel(ti[fi,d], tj[fj,d])
// One block per pair; 288 threads, one per (fi, fj, o) task.
// ---------------------------------------------------------------------------
__global__ __launch_bounds__(COMBO2)
void build_lut_kernel(const float* __restrict__ tables,
                      const float* __restrict__ Wsmall,
                      const float* __restrict__ Wconcat,
                      const float* __restrict__ aw)
{
    const int p = blockIdx.x;

    // pair p -> (i, j) of triu(N_COLS, k=1), row-major order
    int i = 0, r = p, c = N_COLS - 1;
    while (r >= c) { r -= c; ++i; --c; }
    const int j = i + 1 + r;

    // selected primitive (arch_weights is exact one-hot of 0.0 / 1.0)
    int k = 0;
#pragma unroll
    for (int t = 0; t < N_PRIM; ++t)
        if (aw[p * N_PRIM + t] > 0.5f) k = t;

    // stage the 12 candidate embedding vectors for columns i and j
    __shared__ float shi[EMB][DVEC + 1];   // +1 pad: kill 64-float-stride bank conflicts
    __shared__ float shj[EMB][DVEC + 1];
    for (int e = threadIdx.x; e < EMB * DVEC; e += blockDim.x) {
        const int row = e >> 6, d = e & 63;
        shi[row][d] = tables[(i * EMB + row) * DVEC + d];
        shj[row][d] = tables[(j * EMB + row) * DVEC + d];
    }
    __syncthreads();

    const int task  = threadIdx.x;          // 0..287
    const int o     = task & 1;
    const int combo = task >> 1;            // fi*12 + fj
    const int fi    = combo / EMB;
    const int fj    = combo - fi * EMB;

    float acc = 0.0f;
    if (k == 4) {
        const float* w = Wconcat + (p * 2 + o) * (2 * DVEC);
#pragma unroll
        for (int d = 0; d < DVEC; ++d)
            acc += __ldg(&w[d]) * shi[fi][d] + __ldg(&w[DVEC + d]) * shj[fj][d];
    } else {
        const float* w = Wsmall + ((p * 4 + k) * 2 + o) * DVEC;
        if (k == 0) {
#pragma unroll
            for (int d = 0; d < DVEC; ++d)
                acc += __ldg(&w[d]) * (shi[fi][d] + shj[fj][d]);
        } else if (k == 1) {
#pragma unroll
            for (int d = 0; d < DVEC; ++d)
                acc += __ldg(&w[d]) * (shi[fi][d] * shj[fj][d]);
        } else if (k == 2) {
#pragma unroll
            for (int d = 0; d < DVEC; ++d)
                acc += __ldg(&w[d]) * fmaxf(shi[fi][d], shj[fj][d]);
        } else {
#pragma unroll
            for (int d = 0; d < DVEC; ++d)
                acc += __ldg(&w[d]) * fminf(shi[fi][d], shj[fj][d]);
        }
    }
    g_T[p * COMBO2 + task] = acc;
}

// ---------------------------------------------------------------------------
// Kernel 2: out[b, :] = sum_p T[p, f[i_p], f[j_p], :]
// One WARP per batch element; lanes split pairs (8 unrolled, predicated iters).
// feats row lives in a register (lane == column for lane < 22); per-pair
// indices come from __shfl_sync. float2 warp-reduce at the end.
// ---------------------------------------------------------------------------
__global__ __launch_bounds__(256)
void accumulate_kernel(const int* __restrict__ feats,
                       float* __restrict__ out,
                       int B)
{
    __shared__ uchar2 shp[N_PAIRS + 1];
    for (int p = threadIdx.x; p < N_PAIRS; p += 256) {
        int i = 0, r = p, c = N_COLS - 1;
        while (r >= c) { r -= c; ++i; --c; }
        shp[p] = make_uchar2((unsigned char)i, (unsigned char)(i + 1 + r));
    }
    __syncthreads();

    const int lane = threadIdx.x & 31;
    const int warp = threadIdx.x >> 5;
    const int b    = blockIdx.x * 8 + warp;
    const bool brow = (b < B);

    // feats row: lane c holds feats[b, c] for c < 22
    int f = 0;
    if (brow && lane < N_COLS) f = feats[b * N_COLS + lane];

    const float2* __restrict__ T2 = (const float2*)g_T;
    float ax = 0.0f, ay = 0.0f;

#pragma unroll
    for (int it = 0; it < 8; ++it) {
        const int  p     = lane + it * 32;
        const bool valid = (p < N_PAIRS);
        const int  pc    = valid ? p : 0;
        const uchar2 ij  = shp[pc];
        const int fi = __shfl_sync(0xffffffffu, f, ij.x);
        const int fj = __shfl_sync(0xffffffffu, f, ij.y);
        if (brow && valid) {
            const float2 v = __ldg(&T2[pc * (EMB * EMB) + fi * EMB + fj]);
            ax += v.x;
            ay += v.y;
        }
    }

    // warp reduction of the float2
#pragma unroll
    for (int off = 16; off > 0; off >>= 1) {
        ax += __shfl_xor_sync(0xffffffffu, ax, off);
        ay += __shfl_xor_sync(0xffffffffu, ay, off);
    }

    if (brow && lane == 0)
        ((float2*)out)[b] = make_float2(ax, ay);
}

// ---------------------------------------------------------------------------
// Launch: two kernels on the default stream (implicit ordering), graph-safe.
// Inputs (metadata order): feats(i32), tables(f32), W_small(f32),
//                          W_concat(f32), arch_weights(f32)
// ---------------------------------------------------------------------------
extern "C" void kernel_launch(void* const* d_in, const int* in_sizes, int n_in,
                              void* d_out, int out_size)
{
    const int*   feats   = (const int*)  d_in[0];
    const float* tables  = (const float*)d_in[1];
    const float* Wsmall  = (const float*)d_in[2];
    const float* Wconcat = (const float*)d_in[3];
    const float* aw      = (const float*)d_in[4];
    float*       out     = (float*)d_out;

    const int B = in_sizes[0] / N_COLS;   // 4096

    build_lut_kernel<<<N_PAIRS, COMBO2>>>(tables, Wsmall, Wconcat, aw);

    const int nblocks = (B + 7) / 8;      // one warp per batch element
    accumulate_kernel<<<nblocks, 256>>>(feats, out, B);
}

// round 3
// speedup vs baseline: 1.5721x; 1.1353x over previous
#include <cuda_runtime.h>
#include <cuda_bf16.h>
#include <cstdint>

// Problem constants (fixed by the reference)
#define N_COLS  22
#define N_PAIRS 231
#define EMB     12
#define DVEC    64
#define N_PRIM  5
#define COMBO2  (EMB * EMB * 2)   // 288 floats per pair in the LUT

// Scratch: precomputed per-pair lookup table T[p][fi][fj][o]  (266 KB)
__device__ __align__(16) float g_T[N_PAIRS * COMBO2];

// ---------------------------------------------------------------------------
// Kernel 1: build T[p, fi, fj, o] = sum_d w_sel[p,o,d] * op_sel(ti[fi,d], tj[fj,d])
// One block per pair; 288 threads, one per (fi, fj, o) task. float4 inner loop.
// ---------------------------------------------------------------------------
#define ROWSTRIDE (DVEC + 4)      // 68 floats: keeps float4 alignment, shifts banks by 4/row

__global__ __launch_bounds__(COMBO2)
void build_lut_kernel(const float* __restrict__ tables,
                      const float* __restrict__ Wsmall,
                      const float* __restrict__ Wconcat,
                      const float* __restrict__ aw)
{
    const int p = blockIdx.x;

    // pair p -> (i, j) of triu(N_COLS, k=1), row-major order
    int i = 0, r = p, c = N_COLS - 1;
    while (r >= c) { r -= c; ++i; --c; }
    const int j = i + 1 + r;

    // selected primitive (arch_weights is exact one-hot of 0.0 / 1.0)
    int k = 0;
#pragma unroll
    for (int t = 0; t < N_PRIM; ++t)
        if (aw[p * N_PRIM + t] > 0.5f) k = t;

    // stage the 12 candidate embedding vectors for columns i and j
    __shared__ float shi[EMB * ROWSTRIDE];
    __shared__ float shj[EMB * ROWSTRIDE];
    for (int e = threadIdx.x; e < EMB * DVEC; e += blockDim.x) {
        const int row = e >> 6, d = e & 63;
        shi[row * ROWSTRIDE + d] = tables[(i * EMB + row) * DVEC + d];
        shj[row * ROWSTRIDE + d] = tables[(j * EMB + row) * DVEC + d];
    }
    __syncthreads();

    const int task  = threadIdx.x;          // 0..287
    const int o     = task & 1;
    const int combo = task >> 1;            // fi*12 + fj
    const int fi    = combo / EMB;
    const int fj    = combo - fi * EMB;

    const float4* __restrict__ pi = (const float4*)&shi[fi * ROWSTRIDE];
    const float4* __restrict__ pj = (const float4*)&shj[fj * ROWSTRIDE];

    float acc = 0.0f;
    if (k == 4) {
        const float4* __restrict__ wa = (const float4*)(Wconcat + (p * 2 + o) * (2 * DVEC));
        const float4* __restrict__ wb = wa + (DVEC / 4);
#pragma unroll
        for (int d = 0; d < DVEC / 4; ++d) {
            const float4 a = pi[d], b = pj[d];
            const float4 u = __ldg(&wa[d]), v = __ldg(&wb[d]);
            acc += u.x * a.x + u.y * a.y + u.z * a.z + u.w * a.w;
            acc += v.x * b.x + v.y * b.y + v.z * b.z + v.w * b.w;
        }
    } else {
        const float4* __restrict__ w = (const float4*)(Wsmall + ((p * 4 + k) * 2 + o) * DVEC);
#pragma unroll
        for (int d = 0; d < DVEC / 4; ++d) {
            const float4 a = pi[d], b = pj[d];
            const float4 u = __ldg(&w[d]);
            float4 z;
            if (k == 0)      { z.x = a.x + b.x; z.y = a.y + b.y; z.z = a.z + b.z; z.w = a.w + b.w; }
            else if (k == 1) { z.x = a.x * b.x; z.y = a.y * b.y; z.z = a.z * b.z; z.w = a.w * b.w; }
            else if (k == 2) { z.x = fmaxf(a.x, b.x); z.y = fmaxf(a.y, b.y); z.z = fmaxf(a.z, b.z); z.w = fmaxf(a.w, b.w); }
            else             { z.x = fminf(a.x, b.x); z.y = fminf(a.y, b.y); z.z = fminf(a.z, b.z); z.w = fminf(a.w, b.w); }
            acc += u.x * z.x + u.y * z.y + u.z * z.z + u.w * z.w;
        }
    }
    g_T[p * COMBO2 + combo * 2 + o] = acc;
}

// ---------------------------------------------------------------------------
// Kernel 2: out[b, :] = sum_p T[p, f[i_p], f[j_p], :]
// lane = batch element (32 per block), warp = pair stripe (p = w, w+8, ...).
// All 32 lanes of a warp gather inside ONE pair's 1.15 KB LUT region
// (~10 L1 lines/load instead of 32). Cross-warp reduce through SMEM.
// ---------------------------------------------------------------------------
__global__ __launch_bounds__(256)
void accumulate_kernel(const int* __restrict__ feats,
                       float* __restrict__ out,
                       int B)
{
    __shared__ int    shf[32][N_COLS + 1];   // stride 23: coprime with 32 banks
    __shared__ uchar2 shp[N_PAIRS + 1];
    __shared__ float2 shred[8][32];

    const int tid  = threadIdx.x;
    const int lane = tid & 31;
    const int warp = tid >> 5;
    const int bbase = blockIdx.x * 32;

    // coalesced, cooperative load of this block's 32 feats rows
    for (int e = tid; e < 32 * N_COLS; e += 256) {
        const int row = e / N_COLS, col = e - row * N_COLS;
        const int b   = bbase + row;
        shf[row][col] = (b < B) ? feats[b * N_COLS + col] : 0;
    }
    // (i, j) byte table for all pairs
    for (int p = tid; p < N_PAIRS; p += 256) {
        int i = 0, r = p, c = N_COLS - 1;
        while (r >= c) { r -= c; ++i; --c; }
        shp[p] = make_uchar2((unsigned char)i, (unsigned char)(i + 1 + r));
    }
    __syncthreads();

    const float2* __restrict__ T2 = (const float2*)g_T;
    float ax = 0.0f, ay = 0.0f;

    // warp w handles pairs w, w+8, w+16, ... (29 or 28 independent gathers)
#pragma unroll 4
    for (int p = warp; p < N_PAIRS; p += 8) {
        const uchar2 ij = shp[p];
        const int fi = shf[lane][ij.x];
        const int fj = shf[lane][ij.y];
        const float2 v = __ldg(&T2[p * (EMB * EMB) + fi * EMB + fj]);
        ax += v.x;
        ay += v.y;
    }

    shred[warp][lane] = make_float2(ax, ay);
    __syncthreads();

    if (warp == 0) {
        float sx = 0.0f, sy = 0.0f;
#pragma unroll
        for (int w = 0; w < 8; ++w) {
            const float2 s = shred[w][lane];
            sx += s.x;
            sy += s.y;
        }
        const int b = bbase + lane;
        if (b < B) ((float2*)out)[b] = make_float2(sx, sy);
    }
}

// ---------------------------------------------------------------------------
// Launch: two kernels on the default stream (implicit ordering), graph-safe.
// Inputs (metadata order): feats(i32), tables(f32), W_small(f32),
//                          W_concat(f32), arch_weights(f32)
// ---------------------------------------------------------------------------
extern "C" void kernel_launch(void* const* d_in, const int* in_sizes, int n_in,
                              void* d_out, int out_size)
{
    const int*   feats   = (const int*)  d_in[0];
    const float* tables  = (const float*)d_in[1];
    const float* Wsmall  = (const float*)d_in[2];
    const float* Wconcat = (const float*)d_in[3];
    const float* aw      = (const float*)d_in[4];
    float*       out     = (float*)d_out;

    const int B = in_sizes[0] / N_COLS;   // 4096

    build_lut_kernel<<<N_PAIRS, COMBO2>>>(tables, Wsmall, Wconcat, aw);

    const int nblocks = (B + 31) / 32;    // 32 batch elems per block
    accumulate_kernel<<<nblocks, 256>>>(feats, out, B);
}